// round 7
// baseline (speedup 1.0000x reference)
#include <cuda_runtime.h>
#include <cuda_fp16.h>
#include <cstdint>
#include <cstddef>

#define B_SZ  256
#define C_SZ  10
#define N_CAP 1152
#define DIN   8
#define U_SZ  16

// 94.4 MB fp16 scratch for u_hat, layout [b][c][p][n]  (p = u-pair 0..7).
__device__ unsigned int g_uhat_h[(size_t)B_SZ * C_SZ * 8 * N_CAP];

#define FFMA2(d, a, bb, cc) \
    asm("fma.rn.f32x2 %0, %1, %2, %3;" : "=l"(d) : "l"(a), "l"(bb), "l"(cc))
#define DUP2(d, s) \
    asm("mov.b64 %0, {%1, %1};" : "=l"(d) : "r"(s))
// pack (lo, hi) f32 -> f16x2 word
#define F2H2(d, lo, hi) \
    asm("cvt.rn.f16x2.f32 %0, %1, %2;" : "=r"(d) : "f"(hi), "f"(lo))

// ---------------------------------------------------------------------------
// K1: u_hat -> fp16 [b][c][p][n]. Grid (36, 10, 16): 32 n x c x 16 b.
// 256 thr = 2 b-halves x 32 n x 4 u-quads. W slice (8i x 4u) in regs
// (16 f32x2); x in smem (12-word rows, conflict-free LDS.128).
// Dup phases split (xa then xb) to cap live regs; launch_bounds forces
// 4 CTAs/SM.
// ---------------------------------------------------------------------------
__global__ __launch_bounds__(256, 4) void k1_uhat(const float* __restrict__ x,
                                                  const float* __restrict__ W)
{
    __shared__ float xs[16 * 32 * 12];   // 24KB

    const int n0 = blockIdx.x * 32;
    const int c  = blockIdx.y;
    const int b0 = blockIdx.z * 16;

    for (int t = threadIdx.x; t < 512; t += 256) {
        const int b = t >> 5, n = t & 31;
        const float4* g = (const float4*)(x + ((size_t)(b0 + b) * N_CAP + (n0 + n)) * DIN);
        float4 v0 = g[0], v1 = g[1];
        float* d = xs + (b * 32 + n) * 12;
        *(float4*)(d)     = v0;
        *(float4*)(d + 4) = v1;
    }

    const int uq = threadIdx.x & 3;
    const int nl = (threadIdx.x >> 2) & 31;
    const int bl = threadIdx.x >> 7;     // 0..1
    const int n  = n0 + nl;

    unsigned long long wr[16];
    {
        const ulonglong2* Wp = (const ulonglong2*)(W + ((size_t)c * N_CAP + n) * 128);
        #pragma unroll
        for (int i = 0; i < 8; ++i) {
            ulonglong2 w = Wp[i * 4 + uq];
            wr[2 * i]     = w.x;
            wr[2 * i + 1] = w.y;
        }
    }
    __syncthreads();

    unsigned int* op = g_uhat_h +
        (((size_t)(b0 + bl * 8) * C_SZ + c) * 8 + 2 * uq) * N_CAP + n;

    #pragma unroll 4
    for (int s = 0; s < 8; ++s) {
        const int b = bl * 8 + s;
        const float* xp = xs + (b * 32 + nl) * 12;
        unsigned long long a0 = 0ull, a1 = 0ull;
        {   // phase A: first 4 i
            float4 xa = *(const float4*)(xp);
            unsigned long long x0, x1, x2, x3;
            DUP2(x0, __float_as_uint(xa.x));  DUP2(x1, __float_as_uint(xa.y));
            DUP2(x2, __float_as_uint(xa.z));  DUP2(x3, __float_as_uint(xa.w));
            FFMA2(a0, wr[0], x0, a0);  FFMA2(a1, wr[1], x0, a1);
            FFMA2(a0, wr[2], x1, a0);  FFMA2(a1, wr[3], x1, a1);
            FFMA2(a0, wr[4], x2, a0);  FFMA2(a1, wr[5], x2, a1);
            FFMA2(a0, wr[6], x3, a0);  FFMA2(a1, wr[7], x3, a1);
        }
        {   // phase B: last 4 i
            float4 xb = *(const float4*)(xp + 4);
            unsigned long long x4, x5, x6, x7;
            DUP2(x4, __float_as_uint(xb.x));  DUP2(x5, __float_as_uint(xb.y));
            DUP2(x6, __float_as_uint(xb.z));  DUP2(x7, __float_as_uint(xb.w));
            FFMA2(a0, wr[8],  x4, a0);  FFMA2(a1, wr[9],  x4, a1);
            FFMA2(a0, wr[10], x5, a0);  FFMA2(a1, wr[11], x5, a1);
            FFMA2(a0, wr[12], x6, a0);  FFMA2(a1, wr[13], x6, a1);
            FFMA2(a0, wr[14], x7, a0);  FFMA2(a1, wr[15], x7, a1);
        }
        unsigned int l0, h0, l1, h1;
        asm("mov.b64 {%0, %1}, %2;" : "=r"(l0), "=r"(h0) : "l"(a0));
        asm("mov.b64 {%0, %1}, %2;" : "=r"(l1), "=r"(h1) : "l"(a1));
        __half2 p0 = __floats2half2_rn(__uint_as_float(l0), __uint_as_float(h0));
        __half2 p1 = __floats2half2_rn(__uint_as_float(l1), __uint_as_float(h1));
        op[0]     = *(unsigned int*)&p0;
        op[N_CAP] = *(unsigned int*)&p1;
        op += (size_t)C_SZ * 8 * N_CAP;
    }
}

// ---------------------------------------------------------------------------
// block reduce over 512 threads / 16 warps
// ---------------------------------------------------------------------------
__device__ __forceinline__ float blockReduceSum16(float v, float* scratch)
{
    #pragma unroll
    for (int o = 16; o > 0; o >>= 1) v += __shfl_xor_sync(0xffffffffu, v, o);
    if ((threadIdx.x & 31) == 0) scratch[threadIdx.x >> 5] = v;
    __syncthreads();
    float r = 0.f;
    #pragma unroll
    for (int i = 0; i < 16; ++i) r += scratch[i];
    __syncthreads();
    return r;
}

// ---------------------------------------------------------------------------
// K2: routing per (b,c). Grid (C, B), 512 thr, 40.7KB smem (3 CTAs/SM).
//  prologue: 2 warps per u-pair row stream global->smem, fused uniform-s0.
//  exp-scan: 2 n per thread via LDS.64; HFMA2 fp16 dot (two 4-chains),
//            f32 exp; c_arr fp32.
//  s-phase:  2 warps per row, f32 FMA; squash in tid<16; w packed to half2.
// ---------------------------------------------------------------------------
__global__ __launch_bounds__(512, 3) void k2_route(float* __restrict__ outp)
{
    extern __shared__ float sm[];
    unsigned int* uh  = (unsigned int*)sm;            // 8 x 1152 words
    float* c_arr = sm + 8 * N_CAP;                    // 1152
    float* red   = c_arr + N_CAP;                     // 32
    float* red2  = red + 32;                          // 16
    unsigned int* w_h = (unsigned int*)(red2 + 16);   // 8 (16B-aligned)

    const int tid  = threadIdx.x;
    const int c    = blockIdx.x;
    const int b    = blockIdx.y;
    const int w    = tid >> 5;
    const int g    = tid & 31;
    const int p    = w >> 1;
    const int ks   = (w & 1) ? 4 : 0;
    const int ke   = (w & 1) ? 9 : 4;
    unsigned int* uhp = uh + p * N_CAP;

    // ---- prologue: stream row p (half each), fused uniform-s0 ----
    {
        const uint4* src = (const uint4*)(g_uhat_h +
                            (((size_t)b * C_SZ + c) * 8 + p) * N_CAP);
        float sx = 0.f, sy = 0.f;
        for (int k = ks; k < ke; ++k) {
            uint4 v = src[k * 32 + g];
            *(uint4*)(uhp + k * 128 + 4 * g) = v;
            float2 a0 = __half22float2(*(__half2*)&v.x);
            float2 a1 = __half22float2(*(__half2*)&v.y);
            float2 a2 = __half22float2(*(__half2*)&v.z);
            float2 a3 = __half22float2(*(__half2*)&v.w);
            sx += (a0.x + a1.x) + (a2.x + a3.x);
            sy += (a0.y + a1.y) + (a2.y + a3.y);
        }
        #pragma unroll
        for (int o = 16; o > 0; o >>= 1) {
            sx += __shfl_xor_sync(0xffffffffu, sx, o);
            sy += __shfl_xor_sync(0xffffffffu, sy, o);
        }
        if (g == 0) { red[2 * w] = sx; red[2 * w + 1] = sy; }
    }
    __syncthreads();

    float vprev = 0.f;
    if (tid < 16) {
        const int pp = tid >> 1, comp = tid & 1;
        float s_u = (red[4 * pp + comp] + red[4 * pp + 2 + comp])
                    * (1.0f / (float)N_CAP);
        float sq = s_u * s_u;
        sq += __shfl_xor_sync(0x0000ffffu, sq, 1, 16);
        sq += __shfl_xor_sync(0x0000ffffu, sq, 2, 16);
        sq += __shfl_xor_sync(0x0000ffffu, sq, 4, 16);
        sq += __shfl_xor_sync(0x0000ffffu, sq, 8, 16);
        float scale = sq / ((1.0f + sq) * sqrtf(sq + 1e-9f));
        vprev = scale * s_u;                                  // v0
        float vhi = __shfl_down_sync(0x0000ffffu, vprev, 1, 16);
        if ((tid & 1) == 0) {
            unsigned int hw; F2H2(hw, vprev, vhi);
            w_h[tid >> 1] = hw;
        }
    }
    __syncthreads();

    #pragma unroll
    for (int it = 1; it < 3; ++it) {
        // ---- exp-scan: 2 n per thread, HFMA2 dot ----
        uint4 wA = *(const uint4*)(w_h);
        uint4 wB = *(const uint4*)(w_h + 4);
        const __half2 w0 = *(__half2*)&wA.x, w1 = *(__half2*)&wA.y;
        const __half2 w2 = *(__half2*)&wA.z, w3 = *(__half2*)&wA.w;
        const __half2 w4 = *(__half2*)&wB.x, w5 = *(__half2*)&wB.y;
        const __half2 w6 = *(__half2*)&wB.z, w7 = *(__half2*)&wB.w;
        const __half2 z = __float2half2_rn(0.f);

        float ls = 0.f;
        for (int m = tid; m < N_CAP / 2; m += 512) {
            const unsigned int* base = uh + 2 * m;
            uint2 d0 = *(const uint2*)(base);
            uint2 d1 = *(const uint2*)(base + 1 * N_CAP);
            uint2 d2 = *(const uint2*)(base + 2 * N_CAP);
            uint2 d3 = *(const uint2*)(base + 3 * N_CAP);
            uint2 d4 = *(const uint2*)(base + 4 * N_CAP);
            uint2 d5 = *(const uint2*)(base + 5 * N_CAP);
            uint2 d6 = *(const uint2*)(base + 6 * N_CAP);
            uint2 d7 = *(const uint2*)(base + 7 * N_CAP);
            // n = 2m : two 4-term fp16 chains
            __half2 aa = __hfma2(*(__half2*)&d0.x, w0, z);
            aa = __hfma2(*(__half2*)&d1.x, w1, aa);
            aa = __hfma2(*(__half2*)&d2.x, w2, aa);
            aa = __hfma2(*(__half2*)&d3.x, w3, aa);
            __half2 ac = __hfma2(*(__half2*)&d4.x, w4, z);
            ac = __hfma2(*(__half2*)&d5.x, w5, ac);
            ac = __hfma2(*(__half2*)&d6.x, w6, ac);
            ac = __hfma2(*(__half2*)&d7.x, w7, ac);
            // n = 2m+1
            __half2 ab = __hfma2(*(__half2*)&d0.y, w0, z);
            ab = __hfma2(*(__half2*)&d1.y, w1, ab);
            ab = __hfma2(*(__half2*)&d2.y, w2, ab);
            ab = __hfma2(*(__half2*)&d3.y, w3, ab);
            __half2 ad = __hfma2(*(__half2*)&d4.y, w4, z);
            ad = __hfma2(*(__half2*)&d5.y, w5, ad);
            ad = __hfma2(*(__half2*)&d6.y, w6, ad);
            ad = __hfma2(*(__half2*)&d7.y, w7, ad);

            float da = (__low2float(aa) + __high2float(aa))
                     + (__low2float(ac) + __high2float(ac));
            float db = (__low2float(ab) + __high2float(ab))
                     + (__low2float(ad) + __high2float(ad));
            float ea = __expf(da), eb = __expf(db);
            *(float2*)(c_arr + 2 * m) = make_float2(ea, eb);
            ls += ea + eb;
        }
        float inv = 1.0f / blockReduceSum16(ls, red2);  // syncs publish c_arr

        // ---- s-phase: 2 warps per row, f32 FMA ----
        float sx = 0.f, sy = 0.f;
        for (int k = ks; k < ke; ++k) {
            uint4 hv = *(const uint4*)(uhp + k * 128 + 4 * g);
            float4 cv = *(const float4*)(c_arr + k * 128 + 4 * g);
            float2 v0 = __half22float2(*(__half2*)&hv.x);
            float2 v1 = __half22float2(*(__half2*)&hv.y);
            float2 v2 = __half22float2(*(__half2*)&hv.z);
            float2 v3 = __half22float2(*(__half2*)&hv.w);
            sx = fmaf(cv.x, v0.x, sx);  sy = fmaf(cv.x, v0.y, sy);
            sx = fmaf(cv.y, v1.x, sx);  sy = fmaf(cv.y, v1.y, sy);
            sx = fmaf(cv.z, v2.x, sx);  sy = fmaf(cv.z, v2.y, sy);
            sx = fmaf(cv.w, v3.x, sx);  sy = fmaf(cv.w, v3.y, sy);
        }
        #pragma unroll
        for (int o = 16; o > 0; o >>= 1) {
            sx += __shfl_xor_sync(0xffffffffu, sx, o);
            sy += __shfl_xor_sync(0xffffffffu, sy, o);
        }
        if (g == 0) { red[2 * w] = sx; red[2 * w + 1] = sy; }
        __syncthreads();

        // ---- squash ----
        if (tid < 16) {
            const int pp = tid >> 1, comp = tid & 1;
            float s_u = (red[4 * pp + comp] + red[4 * pp + 2 + comp]) * inv;
            float sq = s_u * s_u;
            sq += __shfl_xor_sync(0x0000ffffu, sq, 1, 16);
            sq += __shfl_xor_sync(0x0000ffffu, sq, 2, 16);
            sq += __shfl_xor_sync(0x0000ffffu, sq, 4, 16);
            sq += __shfl_xor_sync(0x0000ffffu, sq, 8, 16);
            float scale = sq / ((1.0f + sq) * sqrtf(sq + 1e-9f));
            float vcur = scale * s_u;
            if (it == 1) {
                float wn = vprev + vcur;      // b2 weights via linearity
                float whi = __shfl_down_sync(0x0000ffffu, wn, 1, 16);
                if ((tid & 1) == 0) {
                    unsigned int hw; F2H2(hw, wn, whi);
                    w_h[tid >> 1] = hw;
                }
            } else {
                outp[((size_t)b * C_SZ + c) * U_SZ + tid] = vcur;
            }
        }
        __syncthreads();
    }
}

// ---------------------------------------------------------------------------
extern "C" void kernel_launch(void* const* d_in, const int* in_sizes, int n_in,
                              void* d_out, int out_size)
{
    const float* x = (const float*)d_in[0];
    const float* W = (const float*)d_in[1];
    if (n_in >= 2 && in_sizes[0] == C_SZ * N_CAP * DIN * U_SZ &&
        in_sizes[1] == B_SZ * N_CAP * DIN) {
        const float* t = x; x = W; W = t;
    }

    const size_t smem2 =
        (size_t)(8 * N_CAP + N_CAP + 32 + 16 + 8) * sizeof(float); // 41,696B
    cudaFuncSetAttribute(k2_route, cudaFuncAttributeMaxDynamicSharedMemorySize,
                         (int)smem2);

    k1_uhat<<<dim3(N_CAP / 32, C_SZ, B_SZ / 16), 256>>>(x, W);
    k2_route<<<dim3(C_SZ, B_SZ), 512, smem2>>>((float*)d_out);
}

// round 8
// speedup vs baseline: 1.2962x; 1.2962x over previous
#include <cuda_runtime.h>
#include <cuda_fp16.h>
#include <cstdint>
#include <cstddef>

#define B_SZ  256
#define C_SZ  10
#define N_CAP 1152
#define DIN   8
#define U_SZ  16

// 94.4 MB fp16 scratch, layout [b][c][q][n] as uint2 (q = u-quad 0..3,
// each uint2 = 4 halves = u 4q..4q+3).
__device__ __align__(16) uint2 g_uhat2[(size_t)B_SZ * C_SZ * 4 * N_CAP];

#define FFMA2(d, a, bb, cc) \
    asm("fma.rn.f32x2 %0, %1, %2, %3;" : "=l"(d) : "l"(a), "l"(bb), "l"(cc))
#define DUP2(d, s) \
    asm("mov.b64 %0, {%1, %1};" : "=l"(d) : "r"(s))
#define F2H2(d, lo, hi) \
    asm("cvt.rn.f16x2.f32 %0, %1, %2;" : "=r"(d) : "f"(hi), "f"(lo))

__device__ __forceinline__ __half2 u2h2(unsigned int v) { return *(__half2*)&v; }

// ---------------------------------------------------------------------------
// K1: u_hat -> fp16 [b][c][q][n] uint2.  (R5 structure, STG.64 store.)
// Grid (36, 10, 8). 256 thr = 2 b-halves x 32 n x 4 u-quads.
// W slice (8i x 4u) in regs (16 f32x2); x staged in smem (12-word rows).
// ---------------------------------------------------------------------------
__global__ __launch_bounds__(256) void k1_uhat(const float* __restrict__ x,
                                               const float* __restrict__ W)
{
    __shared__ float xs[32 * 32 * 12];   // 48KB

    const int n0 = blockIdx.x * 32;
    const int c  = blockIdx.y;
    const int b0 = blockIdx.z * 32;

    for (int t = threadIdx.x; t < 1024; t += 256) {
        const int b = t >> 5, n = t & 31;
        const float4* g = (const float4*)(x + ((size_t)(b0 + b) * N_CAP + (n0 + n)) * DIN);
        float4 v0 = g[0], v1 = g[1];
        float* d = xs + (b * 32 + n) * 12;
        *(float4*)(d)     = v0;
        *(float4*)(d + 4) = v1;
    }

    const int uq = threadIdx.x & 3;
    const int nl = (threadIdx.x >> 2) & 31;
    const int bl = threadIdx.x >> 7;     // 0..1
    const int n  = n0 + nl;

    unsigned long long wr[16];
    {
        const ulonglong2* Wp = (const ulonglong2*)(W + ((size_t)c * N_CAP + n) * 128);
        #pragma unroll
        for (int i = 0; i < 8; ++i) {
            ulonglong2 w = Wp[i * 4 + uq];
            wr[2 * i]     = w.x;     // u pair (4uq, 4uq+1)
            wr[2 * i + 1] = w.y;     // u pair (4uq+2, 4uq+3)
        }
    }
    __syncthreads();

    uint2* op = g_uhat2 +
        (((size_t)(b0 + bl * 16) * C_SZ + c) * 4 + uq) * N_CAP + n;

    #pragma unroll 4
    for (int s = 0; s < 16; ++s) {
        const int b = bl * 16 + s;
        const float* xp = xs + (b * 32 + nl) * 12;
        float4 xa = *(const float4*)(xp);
        float4 xb = *(const float4*)(xp + 4);

        unsigned long long x0, x1, x2, x3, x4, x5, x6, x7;
        DUP2(x0, __float_as_uint(xa.x));  DUP2(x1, __float_as_uint(xa.y));
        DUP2(x2, __float_as_uint(xa.z));  DUP2(x3, __float_as_uint(xa.w));
        DUP2(x4, __float_as_uint(xb.x));  DUP2(x5, __float_as_uint(xb.y));
        DUP2(x6, __float_as_uint(xb.z));  DUP2(x7, __float_as_uint(xb.w));

        unsigned long long a0 = 0ull, a1 = 0ull;
        FFMA2(a0, wr[0],  x0, a0);  FFMA2(a1, wr[1],  x0, a1);
        FFMA2(a0, wr[2],  x1, a0);  FFMA2(a1, wr[3],  x1, a1);
        FFMA2(a0, wr[4],  x2, a0);  FFMA2(a1, wr[5],  x2, a1);
        FFMA2(a0, wr[6],  x3, a0);  FFMA2(a1, wr[7],  x3, a1);
        FFMA2(a0, wr[8],  x4, a0);  FFMA2(a1, wr[9],  x4, a1);
        FFMA2(a0, wr[10], x5, a0);  FFMA2(a1, wr[11], x5, a1);
        FFMA2(a0, wr[12], x6, a0);  FFMA2(a1, wr[13], x6, a1);
        FFMA2(a0, wr[14], x7, a0);  FFMA2(a1, wr[15], x7, a1);

        unsigned int l0, h0, l1, h1;
        asm("mov.b64 {%0, %1}, %2;" : "=r"(l0), "=r"(h0) : "l"(a0));
        asm("mov.b64 {%0, %1}, %2;" : "=r"(l1), "=r"(h1) : "l"(a1));
        __half2 p0 = __floats2half2_rn(__uint_as_float(l0), __uint_as_float(h0));
        __half2 p1 = __floats2half2_rn(__uint_as_float(l1), __uint_as_float(h1));
        uint2 st;
        st.x = *(unsigned int*)&p0;      // u 4uq, 4uq+1
        st.y = *(unsigned int*)&p1;      // u 4uq+2, 4uq+3
        *op = st;                        // one STG.64
        op += (size_t)C_SZ * 4 * N_CAP;
    }
}

// ---------------------------------------------------------------------------
__device__ __forceinline__ float blockReduceSum(float v, float* scratch)
{
    #pragma unroll
    for (int o = 16; o > 0; o >>= 1) v += __shfl_xor_sync(0xffffffffu, v, o);
    if ((threadIdx.x & 31) == 0) scratch[threadIdx.x >> 5] = v;
    __syncthreads();
    float r = 0.f;
    #pragma unroll
    for (int i = 0; i < 8; ++i) r += scratch[i];
    __syncthreads();
    return r;
}

// ---------------------------------------------------------------------------
// K2: routing per (b,c). Grid (C, B), 256 thr, 37.5KB smem, 5 CTAs/SM.
//  prologue: 2 warps per u-quad row stream global->smem, fused uniform-s0.
//  it=1,2:  ONE fused n-scan: 4 LDS.64 -> HFMA2 dot -> exp -> fp32 s-accum
//           into acc[16]; butterfly warp-reduce; squash.  No c_arr.
// ---------------------------------------------------------------------------
__global__ __launch_bounds__(256, 5) void k2_route(float* __restrict__ outp)
{
    extern __shared__ float sm[];
    unsigned int* uh  = (unsigned int*)sm;            // 4 rows x 2304 words
    float* red  = sm + 4 * 2304;                      // 128
    float* red2 = red + 128;                          // 8
    unsigned int* w_h = (unsigned int*)(red2 + 8);    // 8 words (16B aligned)

    const int tid = threadIdx.x;
    const int c   = blockIdx.x;
    const int b   = blockIdx.y;
    const int w   = tid >> 5;
    const int g   = tid & 31;
    const int q   = w >> 1;
    const int hf  = w & 1;

    // ---- prologue: stream row q (half per warp), fused uniform-s0 ----
    {
        const uint4* src = (const uint4*)(g_uhat2 +
                            (((size_t)b * C_SZ + c) * 4 + q) * N_CAP);
        uint4* dst = (uint4*)(uh + q * 2304);
        float s0 = 0.f, s1 = 0.f, s2 = 0.f, s3 = 0.f;
        const int base = hf * 288;
        #pragma unroll
        for (int i = 0; i < 9; ++i) {
            uint4 v = src[base + i * 32 + g];      // 2 n of quad q
            dst[base + i * 32 + g] = v;
            float2 a  = __half22float2(u2h2(v.x)); // n,   u 4q..4q+1
            float2 bb = __half22float2(u2h2(v.y)); // n,   u 4q+2..4q+3
            float2 cc = __half22float2(u2h2(v.z)); // n+1
            float2 dd = __half22float2(u2h2(v.w));
            s0 += a.x + cc.x;  s1 += a.y + cc.y;
            s2 += bb.x + dd.x; s3 += bb.y + dd.y;
        }
        #pragma unroll
        for (int o = 16; o > 0; o >>= 1) {
            s0 += __shfl_xor_sync(0xffffffffu, s0, o);
            s1 += __shfl_xor_sync(0xffffffffu, s1, o);
            s2 += __shfl_xor_sync(0xffffffffu, s2, o);
            s3 += __shfl_xor_sync(0xffffffffu, s3, o);
        }
        if (g == 0) {
            red[w * 4 + 0] = s0;  red[w * 4 + 1] = s1;
            red[w * 4 + 2] = s2;  red[w * 4 + 3] = s3;
        }
    }
    __syncthreads();

    float vprev = 0.f;
    if (tid < 16) {
        const int qq = tid >> 2, ii = tid & 3;
        float s_u = (red[(2 * qq) * 4 + ii] + red[(2 * qq + 1) * 4 + ii])
                    * (1.0f / (float)N_CAP);
        float sq = s_u * s_u;
        sq += __shfl_xor_sync(0x0000ffffu, sq, 1, 16);
        sq += __shfl_xor_sync(0x0000ffffu, sq, 2, 16);
        sq += __shfl_xor_sync(0x0000ffffu, sq, 4, 16);
        sq += __shfl_xor_sync(0x0000ffffu, sq, 8, 16);
        float scale = sq / ((1.0f + sq) * sqrtf(sq + 1e-9f));
        vprev = scale * s_u;                     // v0, u = tid
        float vhi = __shfl_down_sync(0x0000ffffu, vprev, 1, 16);
        if ((tid & 1) == 0) {
            unsigned int hw; F2H2(hw, vprev, vhi);
            w_h[tid >> 1] = hw;                  // w_h[j] = (v_2j, v_2j+1)
        }
    }
    __syncthreads();

    #pragma unroll
    for (int it = 1; it < 3; ++it) {
        uint4 wA = *(const uint4*)(w_h);
        uint4 wB = *(const uint4*)(w_h + 4);
        const __half2 w0 = u2h2(wA.x), w1 = u2h2(wA.y);
        const __half2 w2 = u2h2(wA.z), w3 = u2h2(wA.w);
        const __half2 w4 = u2h2(wB.x), w5 = u2h2(wB.y);
        const __half2 w6 = u2h2(wB.z), w7 = u2h2(wB.w);
        const __half2 z = __float2half2_rn(0.f);

        float acc[16];
        #pragma unroll
        for (int u = 0; u < 16; ++u) acc[u] = 0.f;
        float ls = 0.f;

        // ---- fused scan: dot(HFMA2) -> exp -> fp32 s-accum ----
        for (int n = tid; n < N_CAP; n += 256) {
            uint2 d0 = *(const uint2*)(uh + 0 * 2304 + 2 * n);
            uint2 d1 = *(const uint2*)(uh + 1 * 2304 + 2 * n);
            uint2 d2 = *(const uint2*)(uh + 2 * 2304 + 2 * n);
            uint2 d3 = *(const uint2*)(uh + 3 * 2304 + 2 * n);

            __half2 aa = __hfma2(u2h2(d0.x), w0, z);
            aa = __hfma2(u2h2(d0.y), w1, aa);
            aa = __hfma2(u2h2(d1.x), w2, aa);
            aa = __hfma2(u2h2(d1.y), w3, aa);
            __half2 ac = __hfma2(u2h2(d2.x), w4, z);
            ac = __hfma2(u2h2(d2.y), w5, ac);
            ac = __hfma2(u2h2(d3.x), w6, ac);
            ac = __hfma2(u2h2(d3.y), w7, ac);
            float dot = (__low2float(aa) + __high2float(aa))
                      + (__low2float(ac) + __high2float(ac));
            float e = __expf(dot);
            ls += e;

            float2 v;
            v = __half22float2(u2h2(d0.x));
            acc[0]  = fmaf(e, v.x, acc[0]);   acc[1]  = fmaf(e, v.y, acc[1]);
            v = __half22float2(u2h2(d0.y));
            acc[2]  = fmaf(e, v.x, acc[2]);   acc[3]  = fmaf(e, v.y, acc[3]);
            v = __half22float2(u2h2(d1.x));
            acc[4]  = fmaf(e, v.x, acc[4]);   acc[5]  = fmaf(e, v.y, acc[5]);
            v = __half22float2(u2h2(d1.y));
            acc[6]  = fmaf(e, v.x, acc[6]);   acc[7]  = fmaf(e, v.y, acc[7]);
            v = __half22float2(u2h2(d2.x));
            acc[8]  = fmaf(e, v.x, acc[8]);   acc[9]  = fmaf(e, v.y, acc[9]);
            v = __half22float2(u2h2(d2.y));
            acc[10] = fmaf(e, v.x, acc[10]);  acc[11] = fmaf(e, v.y, acc[11]);
            v = __half22float2(u2h2(d3.x));
            acc[12] = fmaf(e, v.x, acc[12]);  acc[13] = fmaf(e, v.y, acc[13]);
            v = __half22float2(u2h2(d3.y));
            acc[14] = fmaf(e, v.x, acc[14]);  acc[15] = fmaf(e, v.y, acc[15]);
        }

        // ---- vector-halving butterfly: 16 accums over warp ----
        #pragma unroll
        for (int k = 0; k < 4; ++k) {
            const int o = 1 << k;
            const int h = 8 >> k;                 // half-length this stage
            const bool hi = (g >> k) & 1;
            #pragma unroll
            for (int j = 0; j < h; ++j) {
                float send = hi ? acc[j] : acc[j + h];
                float r = __shfl_xor_sync(0xffffffffu, send, o);
                acc[j] = (hi ? acc[j + h] : acc[j]) + r;
            }
        }
        acc[0] += __shfl_xor_sync(0xffffffffu, acc[0], 16);
        // u owned by lane: bit-reverse of (g & 15)
        const int u_own = ((g & 1) << 3) | (((g >> 1) & 1) << 2)
                        | (((g >> 2) & 1) << 1) | ((g >> 3) & 1);
        if (g < 16) red[w * 16 + u_own] = acc[0];

        float inv = 1.0f / blockReduceSum(ls, red2);  // syncs publish red

        // ---- squash (u = tid) ----
        if (tid < 16) {
            float s_u = 0.f;
            #pragma unroll
            for (int ww = 0; ww < 8; ++ww) s_u += red[ww * 16 + tid];
            s_u *= inv;
            float sq = s_u * s_u;
            sq += __shfl_xor_sync(0x0000ffffu, sq, 1, 16);
            sq += __shfl_xor_sync(0x0000ffffu, sq, 2, 16);
            sq += __shfl_xor_sync(0x0000ffffu, sq, 4, 16);
            sq += __shfl_xor_sync(0x0000ffffu, sq, 8, 16);
            float scale = sq / ((1.0f + sq) * sqrtf(sq + 1e-9f));
            float vcur = scale * s_u;
            if (it == 1) {
                float wn = vprev + vcur;          // b2 weights via linearity
                float whi = __shfl_down_sync(0x0000ffffu, wn, 1, 16);
                if ((tid & 1) == 0) {
                    unsigned int hw; F2H2(hw, wn, whi);
                    w_h[tid >> 1] = hw;
                }
            } else {
                outp[((size_t)b * C_SZ + c) * U_SZ + tid] = vcur;
            }
        }
        __syncthreads();
    }
}

// ---------------------------------------------------------------------------
extern "C" void kernel_launch(void* const* d_in, const int* in_sizes, int n_in,
                              void* d_out, int out_size)
{
    const float* x = (const float*)d_in[0];
    const float* W = (const float*)d_in[1];
    if (n_in >= 2 && in_sizes[0] == C_SZ * N_CAP * DIN * U_SZ &&
        in_sizes[1] == B_SZ * N_CAP * DIN) {
        const float* t = x; x = W; W = t;
    }

    const size_t smem2 =
        (size_t)(4 * 2304 + 128 + 8 + 8) * sizeof(float);   // 37,440B
    cudaFuncSetAttribute(k2_route, cudaFuncAttributeMaxDynamicSharedMemorySize,
                         (int)smem2);

    k1_uhat<<<dim3(N_CAP / 32, C_SZ, B_SZ / 32), 256>>>(x, W);
    k2_route<<<dim3(C_SZ, B_SZ), 256, smem2>>>((float*)d_out);
}